// round 7
// baseline (speedup 1.0000x reference)
#include <cuda_runtime.h>

// Problem constants
#define BB   64
#define SD   14
#define NS   196          // S*S
#define CC   32
#define OO   10
#define OPAD 16           // o padded to 16 lanes for warp-local softmax
#define HH   16
#define EPSV 1e-9f
#define LOG2E 1.4426950408889634f
#define SCHUNK 28         // spatial positions per block (= 2 rows of 14)
#define NBLK_S 7          // 196 / 28
#define NPAIR 14          // SCHUNK / 2 (two positions per warp-iteration)

#define BO (BB*OO)        // 640
#define ACC_STRIDE 33     // s0, s1[16], s2[16]

// Scratch: stats accumulators for the 3 passes + softmax params for 2 updates
__device__ float g_acc[3][BO*ACC_STRIDE];
__device__ float g_par[2][BO*ACC_STRIDE];

__global__ void zero_kernel() {
    int i = blockIdx.x * blockDim.x + threadIdx.x;
    if (i < 3 * BO * ACC_STRIDE) ((float*)g_acc)[i] = 0.0f;
}

// One sweep over all capsules.
// FUSED=false: iteration-0 accumulation with uniform rr = 1/O.
// FUSED=true : rr-update (softmax of log_ap) fused with next iteration's stats.
//
// Warp layout: 1 channel x 2 spatial positions x 16 o-slots.
//   lane = half*16 + o ; the two 16-lane halves process two different spatial
//   positions, so ONE xor-butterfly chain (strides 8,4,2,1, confined to each
//   half) normalizes TWO positions at once -> serial softmax cost per position
//   halves vs a 2-channel layout, with identical register usage.
// Block = 256 threads = 8 warps = 8 channels. Grid: (s-chunk, c/8, b).
template<bool FUSED>
__global__ __launch_bounds__(256, 2)
void pass_kernel(const float* __restrict__ pose,
                 const float* __restrict__ act,
                 const float* __restrict__ w,
                 int par_idx, int acc_idx)
{
    const int t = threadIdx.x;
    const int lane = t & 31;
    const int half = lane >> 4;          // which of the 2 positions
    const int o = lane & (OPAD - 1);
    const int c = blockIdx.y * 8 + (t >> 5);
    const int b = blockIdx.z;
    const int sbase = blockIdx.x * SCHUNK;
    const bool live = (o < OO);

    // w[c][o][j][k] -> 16 registers (zeros for dummy o-slots); lanes l and
    // l+16 read identical addresses -> broadcast.
    float wr[16];
    #pragma unroll
    for (int j = 0; j < 16; j++)
        wr[j] = live ? w[(c * OO + o) * 16 + j] : 0.0f;

    // per-(b,o) softmax params in shared, laid out [h][o] (conflict-free
    // broadcast: lanes 0-15 hit banks 0-15; lanes 16-31 same addrs).
    __shared__ float sm_Sh[HH][OPAD];
    __shared__ float sm_MSh[HH][OPAD];
    __shared__ float sm_c1[OPAD];
    float c1r = 0.0f;
    if (FUSED) {
        if (t < OPAD) sm_c1[t] = -1e30f;
        if (t < HH * OPAD) { sm_Sh[t >> 4][t & 15] = 0.0f; sm_MSh[t >> 4][t & 15] = 0.0f; }
        __syncthreads();
        for (int i = t; i < OO * ACC_STRIDE; i += 256) {
            int oo = i / ACC_STRIDE, j = i - oo * ACC_STRIDE;
            float val = g_par[par_idx][(b * OO + oo) * ACC_STRIDE + j];
            if (j == 0)       sm_c1[oo] = val;
            else if (j < 17)  sm_Sh[j - 1][oo] = val;
            else              sm_MSh[j - 17][oo] = val;
        }
        __syncthreads();
        c1r = sm_c1[o];
    }

    // register accumulators
    float a0 = 0.0f, a1[16], a2[16];
    #pragma unroll
    for (int h = 0; h < 16; h++) { a1[h] = 0.0f; a2[h] = 0.0f; }

    const int base_row = sbase / SD;     // sbase is a multiple of 28 = 2 rows

    #pragma unroll 2
    for (int si = 0; si < NPAIR; si++) {
        const int local = 2 * si + half;             // 0..27 within the chunk
        const int s = sbase + local;
        const int cap = (b * NS + s) * CC + c;

        // votes: v[i*4+k] = sum_j pose[i*4+j] * w[j*4+k]
        const float4* p4 = reinterpret_cast<const float4*>(pose) + cap * 4;
        float v[16];
        #pragma unroll
        for (int i = 0; i < 4; i++) {
            float4 p = p4[i];
            #pragma unroll
            for (int k = 0; k < 4; k++) {
                float vv = p.x * wr[k];
                vv = fmaf(p.y, wr[4 + k], vv);
                vv = fmaf(p.z, wr[8 + k], vv);
                vv = fmaf(p.w, wr[12 + k], vv);
                v[i * 4 + k] = vv;
            }
        }
        // coordinate addition: h=0 row coord, h=1 col coord
        const int row1 = (local >= SD) ? 1 : 0;
        v[0] += (base_row + row1 + 0.5f) * (1.0f / SD);
        v[1] += (local - row1 * SD + 0.5f) * (1.0f / SD);

        const float a = act[cap];
        float r;
        if (!FUSED) {
            r = live ? a * (1.0f / OO) : 0.0f;
        } else {
            // log_ap (base-2 scaled): c1 - sum_h ((v-m)^2 * log2e / (2 var))
            float lapA = c1r, lapB = 0.0f;
            #pragma unroll
            for (int h = 0; h < 16; h += 2) {
                float dA = fmaf(v[h],     sm_Sh[h][o],     -sm_MSh[h][o]);
                float dB = fmaf(v[h + 1], sm_Sh[h + 1][o], -sm_MSh[h + 1][o]);
                lapA = fmaf(dA, -dA, lapA);
                lapB = fmaf(dB, -dB, lapB);
            }
            float lap = lapA + lapB;          // dummy lanes: -1e30
            // warp softmax: butterfly confined to each 16-lane half, serving
            // both positions with one chain
            float mx = lap;
            #pragma unroll
            for (int m = 8; m >= 1; m >>= 1)
                mx = fmaxf(mx, __shfl_xor_sync(0xFFFFFFFFu, mx, m));
            float e = exp2f(lap - mx);        // dummy lanes -> 0
            float sum = e;
            #pragma unroll
            for (int m = 8; m >= 1; m >>= 1)
                sum += __shfl_xor_sync(0xFFFFFFFFu, sum, m);
            r = e * __fdividef(a, sum);       // rr * a
        }

        a0 += r;
        #pragma unroll
        for (int h = 0; h < 16; h++) {
            float rv = r * v[h];
            a1[h] += rv;
            a2[h] = fmaf(rv, v[h], a2[h]);
        }
    }

    // pre-reduction: lane o (pos A) and lane o+16 (pos B) hold stats for the
    // same (b,o) -> merge via shfl, halving global atomics.
    a0 += __shfl_down_sync(0xFFFFFFFFu, a0, 16);
    #pragma unroll
    for (int h = 0; h < 16; h++) {
        a1[h] += __shfl_down_sync(0xFFFFFFFFu, a1[h], 16);
        a2[h] += __shfl_down_sync(0xFFFFFFFFu, a2[h], 16);
    }

    // flush accumulators (lower half-warp, live o only)
    if (lane < OO) {
        float* dst = &g_acc[acc_idx][(b * OO + o) * ACC_STRIDE];
        atomicAdd(dst, a0);
        #pragma unroll
        for (int h = 0; h < 16; h++) {
            atomicAdd(dst + 1 + h, a1[h]);
            atomicAdd(dst + 17 + h, a2[h]);
        }
    }
}

// Per-(b,o) M-step: mean/var/activation; emits either softmax params for the
// next sweep or the final outputs.
__global__ void m_kernel(const float* __restrict__ beta_a,
                         const float* __restrict__ beta_v,
                         float* __restrict__ out,
                         int acc_idx, int par_idx,
                         float inv_temp, int is_final)
{
    const int idx = threadIdx.x;
    if (idx >= BO) return;
    const int o = idx % OO;
    const float* sacc = &g_acc[acc_idx][idx * ACC_STRIDE];
    const float s0 = sacc[0];
    const float denom = 1.0f / (s0 + EPSV);

    float m[16], var[16];
    float sumlog = 0.0f;
    #pragma unroll
    for (int h = 0; h < 16; h++) {
        float s1 = sacc[1 + h];
        float s2 = sacc[17 + h];
        float mh = s1 * denom;                           // = S1/(S0+eps)
        float num = s2 - 2.0f * mh * s1 + mh * mh * s0;  // sum r(v-m)^2
        float vh = num * denom + EPSV;
        m[h] = mh;
        var[h] = vh;
        sumlog += logf(vh);
    }
    float cost = (16.0f * beta_v[o] + 0.5f * sumlog) * s0;
    float aj = 1.0f / (1.0f + expf(-inv_temp * (beta_a[o] - cost)));

    if (is_final) {
        #pragma unroll
        for (int h = 0; h < 16; h++) out[idx * 16 + h] = m[h];
        out[BO * 16 + idx] = aj;
    } else {
        float* pp = &g_par[par_idx][idx * ACC_STRIDE];
        float c1 = logf(aj + EPSV);
        #pragma unroll
        for (int h = 0; h < 16; h++) {
            c1 -= 0.5f * logf(6.283185307179586f * var[h]);
            float S = sqrtf(LOG2E / (2.0f * var[h]));
            pp[1 + h] = S;
            pp[17 + h] = m[h] * S;
        }
        pp[0] = c1 * LOG2E;
    }
}

extern "C" void kernel_launch(void* const* d_in, const int* in_sizes, int n_in,
                              void* d_out, int out_size)
{
    const float* pose = (const float*)d_in[0];
    const float* act  = (const float*)d_in[1];
    const float* w    = (const float*)d_in[2];
    const float* ba   = (const float*)d_in[3];
    const float* bv   = (const float*)d_in[4];
    float* out = (float*)d_out;

    const int nz = 3 * BO * ACC_STRIDE;
    zero_kernel<<<(nz + 255) / 256, 256>>>();

    dim3 grid(NBLK_S, 4, BB);   // s-chunk, c/8, batch

    // inv_temp(it) = 0.01 * (1 - 0.95^(it+1))
    const float it0 = 0.01f * (1.0f - 0.95f);
    const float it1 = 0.01f * (1.0f - 0.95f * 0.95f);
    const float it2 = 0.01f * (1.0f - 0.95f * 0.95f * 0.95f);

    // iteration 0: uniform rr
    pass_kernel<false><<<grid, 256>>>(pose, act, w, 0, 0);
    m_kernel<<<1, BO>>>(ba, bv, out, 0, 0, it0, 0);
    // iteration 1: rr update (from it0 stats) fused with stats accumulation
    pass_kernel<true><<<grid, 256>>>(pose, act, w, 0, 1);
    m_kernel<<<1, BO>>>(ba, bv, out, 1, 1, it1, 0);
    // iteration 2: rr update fused with final stats accumulation
    pass_kernel<true><<<grid, 256>>>(pose, act, w, 1, 2);
    m_kernel<<<1, BO>>>(ba, bv, out, 2, 0, it2, 1);
}

// round 8
// speedup vs baseline: 1.7804x; 1.7804x over previous
#include <cuda_runtime.h>

// Problem constants
#define BB   64
#define SD   14
#define NS   196          // S*S
#define CC   32
#define OO   10
#define OPAD 16           // o padded to 16 lanes for warp-local softmax
#define HH   16
#define EPSV 1e-9f
#define LOG2E 1.4426950408889634f
#define SCHUNK 28         // spatial positions per block (= 2 rows of 14)
#define NBLK_S 7          // 196 / 28
#define CPB  16           // channels per block

#define BO (BB*OO)        // 640
#define ACC_STRIDE 33     // s0, s1[16], s2[16]

// Scratch: stats accumulators for the 3 passes + softmax params for 2 updates
__device__ float g_acc[3][BO*ACC_STRIDE];
__device__ float g_par[2][BO*ACC_STRIDE];

__global__ void zero_kernel() {
    int i = blockIdx.x * blockDim.x + threadIdx.x;
    if (i < 3 * BO * ACC_STRIDE) ((float*)g_acc)[i] = 0.0f;
}

// One sweep over all capsules.  (R4 layout: warp = 2 channels x 16 o-slots,
// butterfly softmax confined to each 16-lane half; block = 256 thr = 16 ch.)
// NEW: the block's pose/act tile is staged through shared memory up front
// (coalesced float4 loads), so the serial per-iteration chain contains LDS
// (29 cyc) instead of L2-latency LDG (~250-600 cyc).
template<bool FUSED>
__global__ __launch_bounds__(256, 2)
void pass_kernel(const float* __restrict__ pose,
                 const float* __restrict__ act,
                 const float* __restrict__ w,
                 int par_idx, int acc_idx)
{
    const int t = threadIdx.x;
    const int o = t & (OPAD - 1);
    const int c_local = t >> 4;                  // 0..15
    const int cbase = blockIdx.y * CPB;
    const int c = cbase + c_local;
    const int b = blockIdx.z;
    const int sbase = blockIdx.x * SCHUNK;
    const bool live = (o < OO);

    // Staged tiles + softmax params (static smem total ~32.5 KB -> 2 blocks/SM)
    __shared__ float4 sm_pose4[SCHUNK * CPB * 4];   // [s][c][4 x float4]
    __shared__ float  sm_act[SCHUNK * CPB];         // [s][c]
    __shared__ float  sm_Sh[HH][OPAD];
    __shared__ float  sm_MSh[HH][OPAD];
    __shared__ float  sm_c1[OPAD];

    // w[c][o][j][k] -> 16 registers (zeros for dummy o-slots)
    float wr[16];
    #pragma unroll
    for (int j = 0; j < 16; j++)
        wr[j] = live ? w[(c * OO + o) * 16 + j] : 0.0f;

    if (FUSED) {
        // dummy-slot init must be ordered before the real param writes
        if (t < OPAD) sm_c1[t] = -1e30f;
        if (t < HH * OPAD) { sm_Sh[t >> 4][t & 15] = 0.0f; sm_MSh[t >> 4][t & 15] = 0.0f; }
        __syncthreads();
    }

    // Cooperative staging: pose tile = 28 pos x 16 ch x 4 float4 = 1792 float4
    {
        const float4* gpose4 = reinterpret_cast<const float4*>(pose);
        #pragma unroll
        for (int k = 0; k < 7; k++) {
            int i = t + k * 256;                 // 0..1791
            int row = i >> 6;                    // position 0..27
            int col = i & 63;                    // float4 within the 64-f4 row
            sm_pose4[row * 64 + col] =
                gpose4[((size_t)(b * NS + sbase + row) * CC + cbase) * 4 + col];
        }
        // act tile: 28 x 16 = 448 floats
        for (int i = t; i < SCHUNK * CPB; i += 256) {
            int row = i >> 4, cc = i & 15;
            sm_act[i] = act[(size_t)(b * NS + sbase + row) * CC + cbase + cc];
        }
    }
    if (FUSED) {
        // real per-(b,o) softmax params, laid out [h][o]
        for (int i = t; i < OO * ACC_STRIDE; i += 256) {
            int oo = i / ACC_STRIDE, j = i - oo * ACC_STRIDE;
            float val = g_par[par_idx][(b * OO + oo) * ACC_STRIDE + j];
            if (j == 0)       sm_c1[oo] = val;
            else if (j < 17)  sm_Sh[j - 1][oo] = val;
            else              sm_MSh[j - 17][oo] = val;
        }
    }
    __syncthreads();
    const float c1r = FUSED ? sm_c1[o] : 0.0f;

    // register accumulators
    float a0 = 0.0f, a1[16], a2[16];
    #pragma unroll
    for (int h = 0; h < 16; h++) { a1[h] = 0.0f; a2[h] = 0.0f; }

    const int base_row = sbase / SD;     // sbase is a multiple of 28 = 2 rows

    #pragma unroll 2
    for (int si = 0; si < SCHUNK; si++) {
        // votes: v[i*4+k] = sum_j pose[i*4+j] * w[j*4+k]   (pose from smem)
        const float4* p4 = &sm_pose4[(si * CPB + c_local) * 4];
        float v[16];
        #pragma unroll
        for (int i = 0; i < 4; i++) {
            float4 p = p4[i];
            #pragma unroll
            for (int k = 0; k < 4; k++) {
                float vv = p.x * wr[k];
                vv = fmaf(p.y, wr[4 + k], vv);
                vv = fmaf(p.z, wr[8 + k], vv);
                vv = fmaf(p.w, wr[12 + k], vv);
                v[i * 4 + k] = vv;
            }
        }
        // coordinate addition: h=0 row coord, h=1 col coord
        const int row1 = (si >= SD) ? 1 : 0;
        v[0] += (base_row + row1 + 0.5f) * (1.0f / SD);
        v[1] += (si - row1 * SD + 0.5f) * (1.0f / SD);

        const float a = sm_act[si * CPB + c_local];
        float r;
        if (!FUSED) {
            r = live ? a * (1.0f / OO) : 0.0f;
        } else {
            // log_ap (base-2 scaled): c1 - sum_h ((v-m)^2 * log2e / (2 var))
            float lapA = c1r, lapB = 0.0f;
            #pragma unroll
            for (int h = 0; h < 16; h += 2) {
                float dA = fmaf(v[h],     sm_Sh[h][o],     -sm_MSh[h][o]);
                float dB = fmaf(v[h + 1], sm_Sh[h + 1][o], -sm_MSh[h + 1][o]);
                lapA = fmaf(dA, -dA, lapA);
                lapB = fmaf(dB, -dB, lapB);
            }
            float lap = lapA + lapB;          // dummy lanes: -1e30
            // warp softmax: butterfly confined to each 16-lane half
            float mx = lap;
            #pragma unroll
            for (int m = 8; m >= 1; m >>= 1)
                mx = fmaxf(mx, __shfl_xor_sync(0xFFFFFFFFu, mx, m));
            float e = exp2f(lap - mx);        // dummy lanes -> 0
            float sum = e;
            #pragma unroll
            for (int m = 8; m >= 1; m >>= 1)
                sum += __shfl_xor_sync(0xFFFFFFFFu, sum, m);
            r = e * __fdividef(a, sum);       // rr * a
        }

        a0 += r;
        #pragma unroll
        for (int h = 0; h < 16; h++) {
            float rv = r * v[h];
            a1[h] += rv;
            a2[h] = fmaf(rv, v[h], a2[h]);
        }
    }

    // pre-reduction: lane o (channel 2w) and lane o+16 (channel 2w+1) hold
    // stats for the same (b,o) -> merge via shfl, halving global atomics.
    a0 += __shfl_down_sync(0xFFFFFFFFu, a0, 16);
    #pragma unroll
    for (int h = 0; h < 16; h++) {
        a1[h] += __shfl_down_sync(0xFFFFFFFFu, a1[h], 16);
        a2[h] += __shfl_down_sync(0xFFFFFFFFu, a2[h], 16);
    }

    // flush accumulators (lower half-warp, live o only)
    if ((t & 31) < OO) {
        float* dst = &g_acc[acc_idx][(b * OO + o) * ACC_STRIDE];
        atomicAdd(dst, a0);
        #pragma unroll
        for (int h = 0; h < 16; h++) {
            atomicAdd(dst + 1 + h, a1[h]);
            atomicAdd(dst + 17 + h, a2[h]);
        }
    }
}

// Per-(b,o) M-step: mean/var/activation; emits either softmax params for the
// next sweep or the final outputs.
__global__ void m_kernel(const float* __restrict__ beta_a,
                         const float* __restrict__ beta_v,
                         float* __restrict__ out,
                         int acc_idx, int par_idx,
                         float inv_temp, int is_final)
{
    const int idx = threadIdx.x;
    if (idx >= BO) return;
    const int o = idx % OO;
    const float* sacc = &g_acc[acc_idx][idx * ACC_STRIDE];
    const float s0 = sacc[0];
    const float denom = 1.0f / (s0 + EPSV);

    float m[16], var[16];
    float sumlog = 0.0f;
    #pragma unroll
    for (int h = 0; h < 16; h++) {
        float s1 = sacc[1 + h];
        float s2 = sacc[17 + h];
        float mh = s1 * denom;                           // = S1/(S0+eps)
        float num = s2 - 2.0f * mh * s1 + mh * mh * s0;  // sum r(v-m)^2
        float vh = num * denom + EPSV;
        m[h] = mh;
        var[h] = vh;
        sumlog += logf(vh);
    }
    float cost = (16.0f * beta_v[o] + 0.5f * sumlog) * s0;
    float aj = 1.0f / (1.0f + expf(-inv_temp * (beta_a[o] - cost)));

    if (is_final) {
        #pragma unroll
        for (int h = 0; h < 16; h++) out[idx * 16 + h] = m[h];
        out[BO * 16 + idx] = aj;
    } else {
        float* pp = &g_par[par_idx][idx * ACC_STRIDE];
        float c1 = logf(aj + EPSV);
        #pragma unroll
        for (int h = 0; h < 16; h++) {
            c1 -= 0.5f * logf(6.283185307179586f * var[h]);
            float S = sqrtf(LOG2E / (2.0f * var[h]));
            pp[1 + h] = S;
            pp[17 + h] = m[h] * S;
        }
        pp[0] = c1 * LOG2E;
    }
}

extern "C" void kernel_launch(void* const* d_in, const int* in_sizes, int n_in,
                              void* d_out, int out_size)
{
    const float* pose = (const float*)d_in[0];
    const float* act  = (const float*)d_in[1];
    const float* w    = (const float*)d_in[2];
    const float* ba   = (const float*)d_in[3];
    const float* bv   = (const float*)d_in[4];
    float* out = (float*)d_out;

    const int nz = 3 * BO * ACC_STRIDE;
    zero_kernel<<<(nz + 255) / 256, 256>>>();

    dim3 grid(NBLK_S, 2, BB);   // s-chunk, c-half, batch  (R4 layout)

    // inv_temp(it) = 0.01 * (1 - 0.95^(it+1))
    const float it0 = 0.01f * (1.0f - 0.95f);
    const float it1 = 0.01f * (1.0f - 0.95f * 0.95f);
    const float it2 = 0.01f * (1.0f - 0.95f * 0.95f * 0.95f);

    // iteration 0: uniform rr
    pass_kernel<false><<<grid, 256>>>(pose, act, w, 0, 0);
    m_kernel<<<1, BO>>>(ba, bv, out, 0, 0, it0, 0);
    // iteration 1: rr update (from it0 stats) fused with stats accumulation
    pass_kernel<true><<<grid, 256>>>(pose, act, w, 0, 1);
    m_kernel<<<1, BO>>>(ba, bv, out, 1, 1, it1, 0);
    // iteration 2: rr update fused with final stats accumulation
    pass_kernel<true><<<grid, 256>>>(pose, act, w, 1, 2);
    m_kernel<<<1, BO>>>(ba, bv, out, 2, 0, it2, 1);
}

// round 10
// speedup vs baseline: 1.8469x; 1.0374x over previous
#include <cuda_runtime.h>

typedef unsigned long long ull;

// Problem constants
#define BB   64
#define SD   14
#define NS   196          // S*S
#define CC   32
#define OO   10
#define OPAD 16           // o padded to 16 lanes for warp-local softmax
#define HH   16
#define EPSV 1e-9f
#define LOG2E 1.4426950408889634f
#define SCHUNK 28         // spatial positions per block (= 2 rows of 14)
#define NBLK_S 7          // 196 / 28
#define CPB  16           // channels per block

#define BO (BB*OO)        // 640
#define ACC_STRIDE 33     // s0, s1[16], s2[16]

// ---- packed f32x2 helpers (FFMA2 path; sm_100+) ----
__device__ __forceinline__ ull pk(float lo, float hi) {
    ull r; asm("mov.b64 %0, {%1, %2};" : "=l"(r) : "f"(lo), "f"(hi)); return r;
}
__device__ __forceinline__ void upk(float& lo, float& hi, ull p) {
    asm("mov.b64 {%0, %1}, %2;" : "=f"(lo), "=f"(hi) : "l"(p));
}
__device__ __forceinline__ ull fma2(ull a, ull b, ull c) {
    ull d; asm("fma.rn.f32x2 %0, %1, %2, %3;" : "=l"(d) : "l"(a), "l"(b), "l"(c)); return d;
}
__device__ __forceinline__ ull mul2(ull a, ull b) {
    ull d; asm("mul.rn.f32x2 %0, %1, %2;" : "=l"(d) : "l"(a), "l"(b)); return d;
}
__device__ __forceinline__ ull add2(ull a, ull b) {
    ull d; asm("add.rn.f32x2 %0, %1, %2;" : "=l"(d) : "l"(a), "l"(b)); return d;
}

// Scratch: stats accumulators for the 3 passes + softmax params for 2 updates
__device__ float g_acc[3][BO*ACC_STRIDE];
__device__ float g_par[2][BO*ACC_STRIDE];

__global__ void zero_kernel() {
    int i = blockIdx.x * blockDim.x + threadIdx.x;
    if (i < 3 * BO * ACC_STRIDE) ((float*)g_acc)[i] = 0.0f;
}

// One sweep over all capsules.  Warp = 2 channels x 16 o-slots, butterfly
// softmax confined to each 16-lane half; block = 256 thr = 16 channels.
// Pose/act staged through smem; all heavy arithmetic in packed f32x2.
template<bool FUSED>
__global__ __launch_bounds__(256, 2)
void pass_kernel(const float* __restrict__ pose,
                 const float* __restrict__ act,
                 const float* __restrict__ w,
                 int par_idx, int acc_idx)
{
    const int t = threadIdx.x;
    const int o = t & (OPAD - 1);
    const int c_local = t >> 4;                  // 0..15
    const int cbase = blockIdx.y * CPB;
    const int c = cbase + c_local;
    const int b = blockIdx.z;
    const int sbase = blockIdx.x * SCHUNK;
    const bool live = (o < OO);

    // Staged tiles + packed softmax params (~33 KB -> 2 blocks/SM, reg-bound)
    __shared__ float4 sm_pose4[SCHUNK * CPB * 4];   // [s][c][4 x float4]
    __shared__ float  sm_act[SCHUNK * CPB];         // [s][c]
    __shared__ ull    sm_Sh2[OPAD][9];              // [o][hp] packed, col-padded
    __shared__ ull    sm_nMSh2[OPAD][9];            // packed, pre-negated
    __shared__ float  sm_c1[OPAD];

    // w[c][o][j][k] -> 8 packed registers wp[j][kp] = (w[j][2kp], w[j][2kp+1])
    ull wp[4][2];
    {
        float wr[16];
        #pragma unroll
        for (int j = 0; j < 16; j++)
            wr[j] = live ? w[(c * OO + o) * 16 + j] : 0.0f;
        #pragma unroll
        for (int j = 0; j < 4; j++)
            #pragma unroll
            for (int kp = 0; kp < 2; kp++)
                wp[j][kp] = pk(wr[j * 4 + 2 * kp], wr[j * 4 + 2 * kp + 1]);
    }

    if (FUSED) {
        // dummy-slot init must be ordered before the real param writes
        if (t < OPAD) sm_c1[t] = -1e30f;
        if (t < OPAD * 9) { sm_Sh2[t / 9][t % 9] = 0ULL; sm_nMSh2[t / 9][t % 9] = 0ULL; }
        __syncthreads();
    }

    // Cooperative staging: pose tile = 28 pos x 16 ch x 4 float4 = 1792 float4
    {
        const float4* gpose4 = reinterpret_cast<const float4*>(pose);
        #pragma unroll
        for (int k = 0; k < 7; k++) {
            int i = t + k * 256;                 // 0..1791
            int row = i >> 6;                    // position 0..27
            int col = i & 63;                    // float4 within the 64-f4 row
            sm_pose4[row * 64 + col] =
                gpose4[((size_t)(b * NS + sbase + row) * CC + cbase) * 4 + col];
        }
        // act tile: 28 x 16 = 448 floats
        for (int i = t; i < SCHUNK * CPB; i += 256) {
            int row = i >> 4, cc = i & 15;
            sm_act[i] = act[(size_t)(b * NS + sbase + row) * CC + cbase + cc];
        }
    }
    if (FUSED) {
        // pack per-(b,o) params: 10 o x 8 pairs, plus c1
        if (t < 80) {
            int oo = t >> 3, hp = t & 7;
            const float* pp = &g_par[par_idx][(b * OO + oo) * ACC_STRIDE];
            sm_Sh2[oo][hp]   = pk(pp[1 + 2 * hp], pp[2 + 2 * hp]);
            sm_nMSh2[oo][hp] = pk(-pp[17 + 2 * hp], -pp[18 + 2 * hp]);
        } else if (t < 90) {
            int oo = t - 80;
            sm_c1[oo] = g_par[par_idx][(b * OO + oo) * ACC_STRIDE];
        }
    }
    __syncthreads();
    const float c1r = FUSED ? sm_c1[o] : 0.0f;

    // packed register accumulators
    float a0 = 0.0f;
    ull a1p[8], a2p[8];
    #pragma unroll
    for (int hp = 0; hp < 8; hp++) { a1p[hp] = 0ULL; a2p[hp] = 0ULL; }

    const int base_row = sbase / SD;     // sbase is a multiple of 28 = 2 rows

    #pragma unroll 2
    for (int si = 0; si < SCHUNK; si++) {
        // votes (packed): v2[i*2+kp] = (v[i*4+2kp], v[i*4+2kp+1])
        const float4* p4 = &sm_pose4[(si * CPB + c_local) * 4];
        ull v2[8];
        #pragma unroll
        for (int i = 0; i < 4; i++) {
            float4 p = p4[i];
            ull px = pk(p.x, p.x), py = pk(p.y, p.y);
            ull pz = pk(p.z, p.z), pw = pk(p.w, p.w);
            #pragma unroll
            for (int kp = 0; kp < 2; kp++) {
                ull tv = mul2(px, wp[0][kp]);
                tv = fma2(py, wp[1][kp], tv);
                tv = fma2(pz, wp[2][kp], tv);
                tv = fma2(pw, wp[3][kp], tv);
                v2[i * 2 + kp] = tv;
            }
        }
        // coordinate addition on (v0, v1) = (row coord, col coord)
        const int row1 = (si >= SD) ? 1 : 0;
        v2[0] = add2(v2[0], pk((base_row + row1 + 0.5f) * (1.0f / SD),
                               (si - row1 * SD + 0.5f) * (1.0f / SD)));

        const float a = sm_act[si * CPB + c_local];
        float r;
        if (!FUSED) {
            r = live ? a * (1.0f / OO) : 0.0f;
        } else {
            // lap = c1 - sum_h d^2,  d = v*Sh - MSh  (all packed)
            ull sqa = 0ULL, sqb = 0ULL;
            #pragma unroll
            for (int hp = 0; hp < 8; hp += 2) {
                ull dA = fma2(v2[hp],     sm_Sh2[o][hp],     sm_nMSh2[o][hp]);
                ull dB = fma2(v2[hp + 1], sm_Sh2[o][hp + 1], sm_nMSh2[o][hp + 1]);
                sqa = fma2(dA, dA, sqa);
                sqb = fma2(dB, dB, sqb);
            }
            float qa0, qa1, qb0, qb1;
            upk(qa0, qa1, sqa); upk(qb0, qb1, sqb);
            float lap = c1r - ((qa0 + qa1) + (qb0 + qb1));  // dummy lanes: -1e30
            // warp softmax: butterfly confined to each 16-lane half
            float mx = lap;
            #pragma unroll
            for (int m = 8; m >= 1; m >>= 1)
                mx = fmaxf(mx, __shfl_xor_sync(0xFFFFFFFFu, mx, m));
            float e = exp2f(lap - mx);        // dummy lanes -> 0
            float sum = e;
            #pragma unroll
            for (int m = 8; m >= 1; m >>= 1)
                sum += __shfl_xor_sync(0xFFFFFFFFu, sum, m);
            r = e * __fdividef(a, sum);       // rr * a
        }

        a0 += r;
        ull r2 = pk(r, r);
        #pragma unroll
        for (int hp = 0; hp < 8; hp++) {
            ull rv = mul2(r2, v2[hp]);
            a1p[hp] = add2(a1p[hp], rv);
            a2p[hp] = fma2(rv, v2[hp], a2p[hp]);
        }
    }

    // unpack accumulators
    float a1[16], a2[16];
    #pragma unroll
    for (int hp = 0; hp < 8; hp++) {
        upk(a1[2 * hp], a1[2 * hp + 1], a1p[hp]);
        upk(a2[2 * hp], a2[2 * hp + 1], a2p[hp]);
    }

    // pre-reduction: lane o (channel 2w) and lane o+16 (channel 2w+1) hold
    // stats for the same (b,o) -> merge via shfl, halving global atomics.
    a0 += __shfl_down_sync(0xFFFFFFFFu, a0, 16);
    #pragma unroll
    for (int h = 0; h < 16; h++) {
        a1[h] += __shfl_down_sync(0xFFFFFFFFu, a1[h], 16);
        a2[h] += __shfl_down_sync(0xFFFFFFFFu, a2[h], 16);
    }

    // flush accumulators (lower half-warp, live o only)
    if ((t & 31) < OO) {
        float* dst = &g_acc[acc_idx][(b * OO + o) * ACC_STRIDE];
        atomicAdd(dst, a0);
        #pragma unroll
        for (int h = 0; h < 16; h++) {
            atomicAdd(dst + 1 + h, a1[h]);
            atomicAdd(dst + 17 + h, a2[h]);
        }
    }
}

// Per-(b,o) M-step: mean/var/activation; emits either softmax params for the
// next sweep or the final outputs.
__global__ void m_kernel(const float* __restrict__ beta_a,
                         const float* __restrict__ beta_v,
                         float* __restrict__ out,
                         int acc_idx, int par_idx,
                         float inv_temp, int is_final)
{
    const int idx = threadIdx.x;
    if (idx >= BO) return;
    const int o = idx % OO;
    const float* sacc = &g_acc[acc_idx][idx * ACC_STRIDE];
    const float s0 = sacc[0];
    const float denom = 1.0f / (s0 + EPSV);

    float m[16], var[16];
    float sumlog = 0.0f;
    #pragma unroll
    for (int h = 0; h < 16; h++) {
        float s1 = sacc[1 + h];
        float s2 = sacc[17 + h];
        float mh = s1 * denom;                           // = S1/(S0+eps)
        float num = s2 - 2.0f * mh * s1 + mh * mh * s0;  // sum r(v-m)^2
        float vh = num * denom + EPSV;
        m[h] = mh;
        var[h] = vh;
        sumlog += logf(vh);
    }
    float cost = (16.0f * beta_v[o] + 0.5f * sumlog) * s0;
    float aj = 1.0f / (1.0f + expf(-inv_temp * (beta_a[o] - cost)));

    if (is_final) {
        #pragma unroll
        for (int h = 0; h < 16; h++) out[idx * 16 + h] = m[h];
        out[BO * 16 + idx] = aj;
    } else {
        float* pp = &g_par[par_idx][idx * ACC_STRIDE];
        float c1 = logf(aj + EPSV);
        #pragma unroll
        for (int h = 0; h < 16; h++) {
            c1 -= 0.5f * logf(6.283185307179586f * var[h]);
            float S = sqrtf(LOG2E / (2.0f * var[h]));
            pp[1 + h] = S;
            pp[17 + h] = m[h] * S;
        }
        pp[0] = c1 * LOG2E;
    }
}

extern "C" void kernel_launch(void* const* d_in, const int* in_sizes, int n_in,
                              void* d_out, int out_size)
{
    const float* pose = (const float*)d_in[0];
    const float* act  = (const float*)d_in[1];
    const float* w    = (const float*)d_in[2];
    const float* ba   = (const float*)d_in[3];
    const float* bv   = (const float*)d_in[4];
    float* out = (float*)d_out;

    const int nz = 3 * BO * ACC_STRIDE;
    zero_kernel<<<(nz + 255) / 256, 256>>>();

    dim3 grid(NBLK_S, 2, BB);   // s-chunk, c-half, batch

    // inv_temp(it) = 0.01 * (1 - 0.95^(it+1))
    const float it0 = 0.01f * (1.0f - 0.95f);
    const float it1 = 0.01f * (1.0f - 0.95f * 0.95f);
    const float it2 = 0.01f * (1.0f - 0.95f * 0.95f * 0.95f);

    // iteration 0: uniform rr
    pass_kernel<false><<<grid, 256>>>(pose, act, w, 0, 0);
    m_kernel<<<1, BO>>>(ba, bv, out, 0, 0, it0, 0);
    // iteration 1: rr update (from it0 stats) fused with stats accumulation
    pass_kernel<true><<<grid, 256>>>(pose, act, w, 0, 1);
    m_kernel<<<1, BO>>>(ba, bv, out, 1, 1, it1, 0);
    // iteration 2: rr update fused with final stats accumulation
    pass_kernel<true><<<grid, 256>>>(pose, act, w, 1, 2);
    m_kernel<<<1, BO>>>(ba, bv, out, 2, 0, it2, 1);
}

// round 11
// speedup vs baseline: 1.9042x; 1.0310x over previous
#include <cuda_runtime.h>

typedef unsigned long long ull;

// Problem constants
#define BB   64
#define SD   14
#define NS   196          // S*S
#define CC   32
#define OO   10
#define OPAD 16           // o padded to 16 lanes for warp-local softmax
#define HH   16
#define EPSV 1e-9f
#define LOG2E 1.4426950408889634f
#define SCHUNK 28         // spatial positions per block (= 2 rows of 14)
#define NBLK_S 7          // 196 / 28
#define CPB  16           // channels per block

#define BO (BB*OO)        // 640
#define ACC_STRIDE 33     // s0, s1[16], s2[16]

// ---- packed f32x2 helpers (FFMA2 path; sm_100+) ----
__device__ __forceinline__ ull pk(float lo, float hi) {
    ull r; asm("mov.b64 %0, {%1, %2};" : "=l"(r) : "f"(lo), "f"(hi)); return r;
}
__device__ __forceinline__ void upk(float& lo, float& hi, ull p) {
    asm("mov.b64 {%0, %1}, %2;" : "=f"(lo), "=f"(hi) : "l"(p));
}
__device__ __forceinline__ ull fma2(ull a, ull b, ull c) {
    ull d; asm("fma.rn.f32x2 %0, %1, %2, %3;" : "=l"(d) : "l"(a), "l"(b), "l"(c)); return d;
}
__device__ __forceinline__ ull mul2(ull a, ull b) {
    ull d; asm("mul.rn.f32x2 %0, %1, %2;" : "=l"(d) : "l"(a), "l"(b)); return d;
}
__device__ __forceinline__ ull add2(ull a, ull b) {
    ull d; asm("add.rn.f32x2 %0, %1, %2;" : "=l"(d) : "l"(a), "l"(b)); return d;
}

// Scratch: stats accumulators for the 3 passes + softmax params for 2 updates
__device__ float g_acc[3][BO*ACC_STRIDE];
__device__ float g_par[2][BO*ACC_STRIDE];

__global__ void zero_kernel() {
    int i = blockIdx.x * blockDim.x + threadIdx.x;
    if (i < 3 * BO * ACC_STRIDE) ((float*)g_acc)[i] = 0.0f;
}

// One sweep over all capsules.  Warp = 2 channels x 16 o-slots, butterfly
// softmax confined to each 16-lane half; block = 256 thr = 16 channels.
// Pose/act staged through smem; heavy arithmetic in packed f32x2.
// c1 params arrive pre-shifted by the per-batch max (m_kernel), so
// exp2f(lap) <= 1 cannot overflow -> NO max butterfly in the common path.
// All-underflow / tiny-sum is caught by a warp-uniform rare fallback.
template<bool FUSED>
__global__ __launch_bounds__(256, 2)
void pass_kernel(const float* __restrict__ pose,
                 const float* __restrict__ act,
                 const float* __restrict__ w,
                 int par_idx, int acc_idx)
{
    const int t = threadIdx.x;
    const int o = t & (OPAD - 1);
    const int c_local = t >> 4;                  // 0..15
    const int cbase = blockIdx.y * CPB;
    const int c = cbase + c_local;
    const int b = blockIdx.z;
    const int sbase = blockIdx.x * SCHUNK;
    const bool live = (o < OO);

    // Staged tiles + packed softmax params (~33 KB -> 2 blocks/SM, reg-bound)
    __shared__ float4 sm_pose4[SCHUNK * CPB * 4];   // [s][c][4 x float4]
    __shared__ float  sm_act[SCHUNK * CPB];         // [s][c]
    __shared__ ull    sm_Sh2[OPAD][9];              // [o][hp] packed, col-padded
    __shared__ ull    sm_nMSh2[OPAD][9];            // packed, pre-negated
    __shared__ float  sm_c1[OPAD];

    // w[c][o][j][k] -> 8 packed registers wp[j][kp] = (w[j][2kp], w[j][2kp+1])
    ull wp[4][2];
    {
        float wr[16];
        #pragma unroll
        for (int j = 0; j < 16; j++)
            wr[j] = live ? w[(c * OO + o) * 16 + j] : 0.0f;
        #pragma unroll
        for (int j = 0; j < 4; j++)
            #pragma unroll
            for (int kp = 0; kp < 2; kp++)
                wp[j][kp] = pk(wr[j * 4 + 2 * kp], wr[j * 4 + 2 * kp + 1]);
    }

    if (FUSED) {
        // dummy-slot init must be ordered before the real param writes
        if (t < OPAD) sm_c1[t] = -1e30f;
        if (t < OPAD * 9) { sm_Sh2[t / 9][t % 9] = 0ULL; sm_nMSh2[t / 9][t % 9] = 0ULL; }
        __syncthreads();
    }

    // Cooperative staging: pose tile = 28 pos x 16 ch x 4 float4 = 1792 float4
    {
        const float4* gpose4 = reinterpret_cast<const float4*>(pose);
        #pragma unroll
        for (int k = 0; k < 7; k++) {
            int i = t + k * 256;                 // 0..1791
            int row = i >> 6;                    // position 0..27
            int col = i & 63;                    // float4 within the 64-f4 row
            sm_pose4[row * 64 + col] =
                gpose4[((size_t)(b * NS + sbase + row) * CC + cbase) * 4 + col];
        }
        // act tile: 28 x 16 = 448 floats
        for (int i = t; i < SCHUNK * CPB; i += 256) {
            int row = i >> 4, cc = i & 15;
            sm_act[i] = act[(size_t)(b * NS + sbase + row) * CC + cbase + cc];
        }
    }
    if (FUSED) {
        // pack per-(b,o) params: 10 o x 8 pairs, plus (pre-shifted) c1
        if (t < 80) {
            int oo = t >> 3, hp = t & 7;
            const float* pp = &g_par[par_idx][(b * OO + oo) * ACC_STRIDE];
            sm_Sh2[oo][hp]   = pk(pp[1 + 2 * hp], pp[2 + 2 * hp]);
            sm_nMSh2[oo][hp] = pk(-pp[17 + 2 * hp], -pp[18 + 2 * hp]);
        } else if (t < 90) {
            int oo = t - 80;
            sm_c1[oo] = g_par[par_idx][(b * OO + oo) * ACC_STRIDE];
        }
    }
    __syncthreads();
    const float c1r = FUSED ? sm_c1[o] : 0.0f;

    // packed register accumulators
    float a0 = 0.0f;
    ull a1p[8], a2p[8];
    #pragma unroll
    for (int hp = 0; hp < 8; hp++) { a1p[hp] = 0ULL; a2p[hp] = 0ULL; }

    const int base_row = sbase / SD;     // sbase is a multiple of 28 = 2 rows

    #pragma unroll 2
    for (int si = 0; si < SCHUNK; si++) {
        // votes (packed): v2[i*2+kp] = (v[i*4+2kp], v[i*4+2kp+1])
        const float4* p4 = &sm_pose4[(si * CPB + c_local) * 4];
        ull v2[8];
        #pragma unroll
        for (int i = 0; i < 4; i++) {
            float4 p = p4[i];
            ull px = pk(p.x, p.x), py = pk(p.y, p.y);
            ull pz = pk(p.z, p.z), pw = pk(p.w, p.w);
            #pragma unroll
            for (int kp = 0; kp < 2; kp++) {
                ull tv = mul2(px, wp[0][kp]);
                tv = fma2(py, wp[1][kp], tv);
                tv = fma2(pz, wp[2][kp], tv);
                tv = fma2(pw, wp[3][kp], tv);
                v2[i * 2 + kp] = tv;
            }
        }
        // coordinate addition on (v0, v1) = (row coord, col coord)
        const int row1 = (si >= SD) ? 1 : 0;
        v2[0] = add2(v2[0], pk((base_row + row1 + 0.5f) * (1.0f / SD),
                               (si - row1 * SD + 0.5f) * (1.0f / SD)));

        const float a = sm_act[si * CPB + c_local];
        float r;
        if (!FUSED) {
            r = live ? a * (1.0f / OO) : 0.0f;
        } else {
            // lap = c1' - sum_h d^2,  d = v*Sh - MSh  (all packed)
            // c1' is pre-shifted so lap <= 0 -> exp2f cannot overflow.
            ull sqa = 0ULL, sqb = 0ULL;
            #pragma unroll
            for (int hp = 0; hp < 8; hp += 2) {
                ull dA = fma2(v2[hp],     sm_Sh2[o][hp],     sm_nMSh2[o][hp]);
                ull dB = fma2(v2[hp + 1], sm_Sh2[o][hp + 1], sm_nMSh2[o][hp + 1]);
                sqa = fma2(dA, dA, sqa);
                sqb = fma2(dB, dB, sqb);
            }
            float qa0, qa1, qb0, qb1;
            upk(qa0, qa1, sqa); upk(qb0, qb1, sqb);
            float lap = c1r - ((qa0 + qa1) + (qb0 + qb1));  // dummy lanes: -1e30
            // NO max pass: direct exp + 16-lane butterfly sum
            float e = exp2f(lap);             // dummy lanes -> 0; <= 1 for live
            float sum = e;
            #pragma unroll
            for (int m = 8; m >= 1; m >>= 1)
                sum += __shfl_xor_sync(0xFFFFFFFFu, sum, m);
            // rare fallback: all-underflow or sum tiny enough that a/sum
            // could overflow -> classic max-normalized softmax (warp-uniform)
            if (__any_sync(0xFFFFFFFFu, sum < 1e-30f)) {
                float mx = lap;
                #pragma unroll
                for (int m = 8; m >= 1; m >>= 1)
                    mx = fmaxf(mx, __shfl_xor_sync(0xFFFFFFFFu, mx, m));
                e = exp2f(lap - mx);
                sum = e;
                #pragma unroll
                for (int m = 8; m >= 1; m >>= 1)
                    sum += __shfl_xor_sync(0xFFFFFFFFu, sum, m);
            }
            r = e * __fdividef(a, sum);       // rr * a
        }

        a0 += r;
        ull r2 = pk(r, r);
        #pragma unroll
        for (int hp = 0; hp < 8; hp++) {
            ull rv = mul2(r2, v2[hp]);
            a1p[hp] = add2(a1p[hp], rv);
            a2p[hp] = fma2(rv, v2[hp], a2p[hp]);
        }
    }

    // unpack accumulators
    float a1[16], a2[16];
    #pragma unroll
    for (int hp = 0; hp < 8; hp++) {
        upk(a1[2 * hp], a1[2 * hp + 1], a1p[hp]);
        upk(a2[2 * hp], a2[2 * hp + 1], a2p[hp]);
    }

    // pre-reduction: lane o (channel 2w) and lane o+16 (channel 2w+1) hold
    // stats for the same (b,o) -> merge via shfl, halving global atomics.
    a0 += __shfl_down_sync(0xFFFFFFFFu, a0, 16);
    #pragma unroll
    for (int h = 0; h < 16; h++) {
        a1[h] += __shfl_down_sync(0xFFFFFFFFu, a1[h], 16);
        a2[h] += __shfl_down_sync(0xFFFFFFFFu, a2[h], 16);
    }

    // flush accumulators (lower half-warp, live o only)
    if ((t & 31) < OO) {
        float* dst = &g_acc[acc_idx][(b * OO + o) * ACC_STRIDE];
        atomicAdd(dst, a0);
        #pragma unroll
        for (int h = 0; h < 16; h++) {
            atomicAdd(dst + 1 + h, a1[h]);
            atomicAdd(dst + 17 + h, a2[h]);
        }
    }
}

// Per-(b,o) M-step: mean/var/activation; emits either softmax params for the
// next sweep or the final outputs.  Non-final: c1 is stored PRE-SHIFTED by
// the per-batch max over o (softmax is shift-invariant), so the pass kernel
// can exponentiate without a max pass.
__global__ void m_kernel(const float* __restrict__ beta_a,
                         const float* __restrict__ beta_v,
                         float* __restrict__ out,
                         int acc_idx, int par_idx,
                         float inv_temp, int is_final)
{
    __shared__ float sc1[BO];
    const int idx = threadIdx.x;
    if (idx >= BO) return;
    const int o = idx % OO;
    const float* sacc = &g_acc[acc_idx][idx * ACC_STRIDE];
    const float s0 = sacc[0];
    const float denom = 1.0f / (s0 + EPSV);

    float m[16], var[16];
    float sumlog = 0.0f;
    #pragma unroll
    for (int h = 0; h < 16; h++) {
        float s1 = sacc[1 + h];
        float s2 = sacc[17 + h];
        float mh = s1 * denom;                           // = S1/(S0+eps)
        float num = s2 - 2.0f * mh * s1 + mh * mh * s0;  // sum r(v-m)^2
        float vh = num * denom + EPSV;
        m[h] = mh;
        var[h] = vh;
        sumlog += logf(vh);
    }
    float cost = (16.0f * beta_v[o] + 0.5f * sumlog) * s0;
    float aj = 1.0f / (1.0f + expf(-inv_temp * (beta_a[o] - cost)));

    if (is_final) {
        #pragma unroll
        for (int h = 0; h < 16; h++) out[idx * 16 + h] = m[h];
        out[BO * 16 + idx] = aj;
    } else {
        float* pp = &g_par[par_idx][idx * ACC_STRIDE];
        float c1 = logf(aj + EPSV);
        #pragma unroll
        for (int h = 0; h < 16; h++) {
            c1 -= 0.5f * logf(6.283185307179586f * var[h]);
            float S = sqrtf(LOG2E / (2.0f * var[h]));
            pp[1 + h] = S;
            pp[17 + h] = m[h] * S;
        }
        float c1l2 = c1 * LOG2E;
        sc1[idx] = c1l2;
        __syncthreads();
        // per-batch max over the 10 output capsules -> shift so c1' <= 0
        const float* row = &sc1[(idx / OO) * OO];
        float mx = row[0];
        #pragma unroll
        for (int oo = 1; oo < OO; oo++) mx = fmaxf(mx, row[oo]);
        pp[0] = c1l2 - mx;
    }
}

extern "C" void kernel_launch(void* const* d_in, const int* in_sizes, int n_in,
                              void* d_out, int out_size)
{
    const float* pose = (const float*)d_in[0];
    const float* act  = (const float*)d_in[1];
    const float* w    = (const float*)d_in[2];
    const float* ba   = (const float*)d_in[3];
    const float* bv   = (const float*)d_in[4];
    float* out = (float*)d_out;

    const int nz = 3 * BO * ACC_STRIDE;
    zero_kernel<<<(nz + 255) / 256, 256>>>();

    dim3 grid(NBLK_S, 2, BB);   // s-chunk, c-half, batch

    // inv_temp(it) = 0.01 * (1 - 0.95^(it+1))
    const float it0 = 0.01f * (1.0f - 0.95f);
    const float it1 = 0.01f * (1.0f - 0.95f * 0.95f);
    const float it2 = 0.01f * (1.0f - 0.95f * 0.95f * 0.95f);

    // iteration 0: uniform rr
    pass_kernel<false><<<grid, 256>>>(pose, act, w, 0, 0);
    m_kernel<<<1, BO>>>(ba, bv, out, 0, 0, it0, 0);
    // iteration 1: rr update (from it0 stats) fused with stats accumulation
    pass_kernel<true><<<grid, 256>>>(pose, act, w, 0, 1);
    m_kernel<<<1, BO>>>(ba, bv, out, 1, 1, it1, 0);
    // iteration 2: rr update fused with final stats accumulation
    pass_kernel<true><<<grid, 256>>>(pose, act, w, 1, 2);
    m_kernel<<<1, BO>>>(ba, bv, out, 2, 0, it2, 1);
}